// round 13
// baseline (speedup 1.0000x reference)
#include <cuda_runtime.h>

// DenselyCnnAttLayer — warp==CTA==row + 256-bit global loads/stores (sm_100+).
// out[b,s,d] = sum_l softmax_m( sum_l' s[b,s,l'] * Ws[s,l',m] )[l] * x_l[b,s,d]
// where s[b,s,l] = sum_d x_l[b,s,d].  B=64, S=512, L=6, D=512, fp32.
//
// R13 vs R12 (ncu 65.9us, DRAM 85.3%): payload moves from 24x LDG.128 to
// 12x LDG.256 (ld.global.cs.v8.f32, PTX ISA 8.7 / sm_100+) and stores from
// 4x STG.128 to 2x STG.256. Halves LSU instruction + request count per warp;
// identical bytes, registers, and semantics. Lane handles 8 consecutive
// floats; warp chunk = 1KB contiguous.
//
// Measured matrix: R1 83.5% | R2 72.5% | R3 84.7% | R4 78.7% | R5 77.9% |
// R6 72.6% | R7 n/a | R8 85.0% | R9 85.4% | R10 83.3% | R11 84.4% |
// R12 85.3% (ncu 65.9us, best). Traffic provably minimal (470MB);
// sitting on the mixed-stream HBM3e ceiling.

#define DD    512
#define LL    6
#define CHNK  2            // float8 chunks per lane per layer (512/32/8)
#define NTHR  32           // ONE warp per CTA

struct f8 { float x0, x1, x2, x3, x4, x5, x6, x7; };

__device__ __forceinline__ f8 ldg256_cs(const float* p) {
    f8 r;
    asm volatile("ld.global.cs.v8.f32 {%0,%1,%2,%3,%4,%5,%6,%7}, [%8];"
                 : "=f"(r.x0), "=f"(r.x1), "=f"(r.x2), "=f"(r.x3),
                   "=f"(r.x4), "=f"(r.x5), "=f"(r.x6), "=f"(r.x7)
                 : "l"(p));
    return r;
}
__device__ __forceinline__ void stg256_cs(float* p, const f8& v) {
    asm volatile("st.global.cs.v8.f32 [%0], {%1,%2,%3,%4,%5,%6,%7,%8};"
                 :: "l"(p),
                    "f"(v.x0), "f"(v.x1), "f"(v.x2), "f"(v.x3),
                    "f"(v.x4), "f"(v.x5), "f"(v.x6), "f"(v.x7)
                 : "memory");
}

__global__ __launch_bounds__(NTHR)
void dense_att_kernel(const float* __restrict__ x0,
                      const float* __restrict__ x1,
                      const float* __restrict__ x2,
                      const float* __restrict__ x3,
                      const float* __restrict__ x4,
                      const float* __restrict__ x5,
                      const float* __restrict__ Ws,   // [S, L, L]
                      float* __restrict__ out)        // [B, S, D]
{
    const int lane = threadIdx.x;
    const int row  = blockIdx.x;             // b*S + s
    const int s    = row & 511;              // S = 512

    // lane handles float8s at d = c*256 + lane*8, c = 0..1 (coalesced, 1KB/warp/chunk)
    const size_t base = (size_t)row * DD + (size_t)lane * 8;

    const float* xs[LL] = {x0, x1, x2, x3, x4, x5};

    // 12 front-batched streaming LDG.256, c-outer/j-inner issue order.
    f8 v[LL][CHNK];
#pragma unroll
    for (int c = 0; c < CHNK; c++) {
#pragma unroll
        for (int j = 0; j < LL; j++) {
            v[j][c] = ldg256_cs(xs[j] + base + c * 256);
        }
    }

    float p[LL];
#pragma unroll
    for (int j = 0; j < LL; j++) {
        float acc = 0.0f;
#pragma unroll
        for (int c = 0; c < CHNK; c++) {
            float a0 = (v[j][c].x0 + v[j][c].x1) + (v[j][c].x2 + v[j][c].x3);
            float a1 = (v[j][c].x4 + v[j][c].x5) + (v[j][c].x6 + v[j][c].x7);
            acc += a0 + a1;
        }
        p[j] = acc;
    }

    // Warp butterfly: all lanes end with the full per-layer sums.
#pragma unroll
    for (int off = 16; off > 0; off >>= 1) {
#pragma unroll
        for (int j = 0; j < LL; j++) {
            p[j] += __shfl_xor_sync(0xffffffffu, p[j], off);
        }
    }

    // Redundant per-lane 6x6 projection + softmax (warp-uniform Ws loads).
    const float* W = Ws + (size_t)s * (LL * LL);
    float logit[LL];
#pragma unroll
    for (int m = 0; m < LL; m++) logit[m] = 0.0f;
#pragma unroll
    for (int l = 0; l < LL; l++) {
        const float sl = p[l];
#pragma unroll
        for (int m = 0; m < LL; m++) {
            logit[m] = fmaf(sl, __ldg(W + l * LL + m), logit[m]);
        }
    }

    float mx = logit[0];
#pragma unroll
    for (int m = 1; m < LL; m++) mx = fmaxf(mx, logit[m]);
    float a[LL];
    float den = 0.0f;
#pragma unroll
    for (int m = 0; m < LL; m++) {
        a[m] = __expf(logit[m] - mx);
        den += a[m];
    }
    const float inv = __frcp_rn(den);
#pragma unroll
    for (int m = 0; m < LL; m++) a[m] *= inv;

    // Weighted combine over layers, 2 coalesced 256-bit streaming stores.
#pragma unroll
    for (int c = 0; c < CHNK; c++) {
        f8 o;
        o.x0 = o.x1 = o.x2 = o.x3 = o.x4 = o.x5 = o.x6 = o.x7 = 0.0f;
#pragma unroll
        for (int j = 0; j < LL; j++) {
            o.x0 = fmaf(a[j], v[j][c].x0, o.x0);
            o.x1 = fmaf(a[j], v[j][c].x1, o.x1);
            o.x2 = fmaf(a[j], v[j][c].x2, o.x2);
            o.x3 = fmaf(a[j], v[j][c].x3, o.x3);
            o.x4 = fmaf(a[j], v[j][c].x4, o.x4);
            o.x5 = fmaf(a[j], v[j][c].x5, o.x5);
            o.x6 = fmaf(a[j], v[j][c].x6, o.x6);
            o.x7 = fmaf(a[j], v[j][c].x7, o.x7);
        }
        stg256_cs(out + base + c * 256, o);
    }
}

extern "C" void kernel_launch(void* const* d_in, const int* in_sizes, int n_in,
                              void* d_out, int out_size)
{
    const float* x0 = (const float*)d_in[0];
    const float* x1 = (const float*)d_in[1];
    const float* x2 = (const float*)d_in[2];
    const float* x3 = (const float*)d_in[3];
    const float* x4 = (const float*)d_in[4];
    const float* x5 = (const float*)d_in[5];
    const float* Ws = (const float*)d_in[6];
    float* out = (float*)d_out;

    const int rows = in_sizes[0] / DD;          // B*S = 32768
    dense_att_kernel<<<rows, NTHR>>>(x0, x1, x2, x3, x4, x5, Ws, out);
}

// round 14
// speedup vs baseline: 1.0005x; 1.0005x over previous
#include <cuda_runtime.h>

// DenselyCnnAttLayer — FINAL kernel (R12 structure, the measured optimum).
// out[b,s,d] = sum_l softmax_m( sum_l' s[b,s,l'] * Ws[s,l',m] )[l] * x_l[b,s,d]
// where s[b,s,l] = sum_d x_l[b,s,d].  B=64, S=512, L=6, D=512, fp32.
//
// One warp == one CTA == one (b,s) row. 24 front-batched streaming LDG.128
// (c-outer/j-inner: first 6 requests hit the 6 distinct input buffers),
// shuffle-tree reduction, redundant per-lane 6x6 projection + softmax,
// 4 coalesced streaming STG.128. Grid 32768 x 32 threads.
//
// Complete measured matrix (13 rounds, all alternatives reverted):
//   R1 block-per-row+barrier 83.5%   R2 smem staging         72.5%
//   R3 warp-per-row          84.7%   R4 persistent stride    78.7%
//   R5 TMA 2-slot ring       77.9%   R6 L2-prefetch x2 rows  72.6%
//   R7 redux.sync.add.f32    absent on sm_103 (integer-only)
//   R8 R3 re-land            85.0%   R9 warp==CTA            85.4%
//   R10 L2::256B hint        83.3%   R11 R9 re-land          84.4%
//   R12 c-outer order        85.3% / ncu 65.9us  <-- THIS KERNEL
//   R13 LDG.256/STG.256      85.4% but ncu 67.4us (longer dep chains)
// Traffic provably minimal: 6 reads + 1 write = 470MB; 65.9us x 6.76TB/s
// = 470MB exactly. Pinned at the mixed-stream HBM3e ceiling (~85% of 8TB/s).

#define DD    512
#define LL    6
#define CHNK  4            // float4 chunks per lane per layer (512/32/4)
#define NTHR  32           // ONE warp per CTA

__global__ __launch_bounds__(NTHR)
void dense_att_kernel(const float* __restrict__ x0,
                      const float* __restrict__ x1,
                      const float* __restrict__ x2,
                      const float* __restrict__ x3,
                      const float* __restrict__ x4,
                      const float* __restrict__ x5,
                      const float* __restrict__ Ws,   // [S, L, L]
                      float* __restrict__ out)        // [B, S, D]
{
    const int lane = threadIdx.x;
    const int row  = blockIdx.x;             // b*S + s
    const int s    = row & 511;              // S = 512

    // lane handles float4s at d = c*128 + lane*4, c = 0..3 (coalesced)
    const size_t base = (size_t)row * DD + (size_t)lane * 4;

    const float* xs[LL] = {x0, x1, x2, x3, x4, x5};

    // 24 front-batched streaming LDG.128, c-outer/j-inner issue order.
    float4 v[LL][CHNK];
#pragma unroll
    for (int c = 0; c < CHNK; c++) {
#pragma unroll
        for (int j = 0; j < LL; j++) {
            v[j][c] = __ldcs(reinterpret_cast<const float4*>(xs[j] + base + c * 128));
        }
    }

    float p[LL];
#pragma unroll
    for (int j = 0; j < LL; j++) {
        float a0 = (v[j][0].x + v[j][0].y) + (v[j][0].z + v[j][0].w);
        float a1 = (v[j][1].x + v[j][1].y) + (v[j][1].z + v[j][1].w);
        float a2 = (v[j][2].x + v[j][2].y) + (v[j][2].z + v[j][2].w);
        float a3 = (v[j][3].x + v[j][3].y) + (v[j][3].z + v[j][3].w);
        p[j] = (a0 + a1) + (a2 + a3);
    }

    // Warp butterfly: all lanes end with the full per-layer sums.
    // (redux.sync.add is integer-only on sm_103 — shuffle tree required.)
#pragma unroll
    for (int off = 16; off > 0; off >>= 1) {
#pragma unroll
        for (int j = 0; j < LL; j++) {
            p[j] += __shfl_xor_sync(0xffffffffu, p[j], off);
        }
    }

    // Redundant per-lane 6x6 projection + softmax (warp-uniform Ws loads;
    // Ws is 73KB total, L2/L1 hot).
    const float* W = Ws + (size_t)s * (LL * LL);
    float logit[LL];
#pragma unroll
    for (int m = 0; m < LL; m++) logit[m] = 0.0f;
#pragma unroll
    for (int l = 0; l < LL; l++) {
        const float sl = p[l];
#pragma unroll
        for (int m = 0; m < LL; m++) {
            logit[m] = fmaf(sl, __ldg(W + l * LL + m), logit[m]);
        }
    }

    float mx = logit[0];
#pragma unroll
    for (int m = 1; m < LL; m++) mx = fmaxf(mx, logit[m]);
    float a[LL];
    float den = 0.0f;
#pragma unroll
    for (int m = 0; m < LL; m++) {
        a[m] = __expf(logit[m] - mx);
        den += a[m];
    }
    const float inv = __frcp_rn(den);
#pragma unroll
    for (int m = 0; m < LL; m++) a[m] *= inv;

    // Weighted combine over layers, 4 coalesced streaming stores.
#pragma unroll
    for (int c = 0; c < CHNK; c++) {
        float4 o;
        o.x = o.y = o.z = o.w = 0.0f;
#pragma unroll
        for (int j = 0; j < LL; j++) {
            o.x = fmaf(a[j], v[j][c].x, o.x);
            o.y = fmaf(a[j], v[j][c].y, o.y);
            o.z = fmaf(a[j], v[j][c].z, o.z);
            o.w = fmaf(a[j], v[j][c].w, o.w);
        }
        __stcs(reinterpret_cast<float4*>(out + base + c * 128), o);
    }
}

extern "C" void kernel_launch(void* const* d_in, const int* in_sizes, int n_in,
                              void* d_out, int out_size)
{
    const float* x0 = (const float*)d_in[0];
    const float* x1 = (const float*)d_in[1];
    const float* x2 = (const float*)d_in[2];
    const float* x3 = (const float*)d_in[3];
    const float* x4 = (const float*)d_in[4];
    const float* x5 = (const float*)d_in[5];
    const float* Ws = (const float*)d_in[6];
    float* out = (float*)d_out;

    const int rows = in_sizes[0] / DD;          // B*S = 32768
    dense_att_kernel<<<rows, NTHR>>>(x0, x1, x2, x3, x4, x5, Ws, out);
}

// round 15
// speedup vs baseline: 1.0050x; 1.0046x over previous
#include <cuda_runtime.h>

// DenselyCnnAttLayer — FINAL kernel (R9, best measured: harness 69.73us).
// out[b,s,d] = sum_l softmax_m( sum_l' s[b,s,l'] * Ws[s,l',m] )[l] * x_l[b,s,d]
// where s[b,s,l] = sum_d x_l[b,s,d].  B=64, S=512, L=6, D=512, fp32.
//
// One warp == one CTA == one (b,s) row. 24 front-batched streaming LDG.128
// into registers, shuffle-tree warp reduction, redundant per-lane 6x6
// projection + softmax, 4 coalesced streaming STG.128. Grid 32768 x 32.
//
// Convergence evidence (14 measured rounds):
//   structure: R1 block+barrier 83.5% | R3 warp-per-row 84.7% | R9 warp==CTA
//     85.4% ncu 66.0us harness 69.73us (BEST) — finer granularity wins.
//   residency: R2 smem staging 72.5% (L1tex pipe contention) — registers win.
//   scheduling: R4 persistent 78.7%, R5 TMA ring 77.9%, R6 prefetch 72.6% —
//     the HW CTA scheduler over 32768 minimal CTAs wins.
//   ISA: R7 redux.f32 absent on sm_103; R10 L2::256B hint 83.3% (worse);
//     R13 LDG.256 85.4% but ncu 67.4us (longer dep chains) — LDG.128.cs wins.
//   re-lands R8/R11/R12/R14: 83.8-85.4%, harness 69.7-70.4us = noise band.
// Physics: occupancy reg-limited at 16 warps/SM, yet DRAM% insensitive from
// 15-29 warps/SM -> latency fully hidden; binding constraint is the HBM3e
// mixed-stream ceiling (~6.7-6.8TB/s, ~85% of 8TB/s spec). Traffic provably
// minimal: 470MB, each element touched once (66.0us x 6.76TB/s = 470MB).

#define DD    512
#define LL    6
#define CHNK  4            // float4 chunks per lane per layer (512/32/4)
#define NTHR  32           // ONE warp per CTA

__global__ __launch_bounds__(NTHR)
void dense_att_kernel(const float* __restrict__ x0,
                      const float* __restrict__ x1,
                      const float* __restrict__ x2,
                      const float* __restrict__ x3,
                      const float* __restrict__ x4,
                      const float* __restrict__ x5,
                      const float* __restrict__ Ws,   // [S, L, L]
                      float* __restrict__ out)        // [B, S, D]
{
    const int lane = threadIdx.x;
    const int row  = blockIdx.x;             // b*S + s
    const int s    = row & 511;              // S = 512

    // lane handles float4s at d = c*128 + lane*4, c = 0..3 (coalesced)
    const size_t base = (size_t)row * DD + (size_t)lane * 4;

    const float* xs[LL] = {x0, x1, x2, x3, x4, x5};

    // 24 front-batched streaming LDG.128 (each element touched exactly once).
    float4 v[LL][CHNK];
#pragma unroll
    for (int j = 0; j < LL; j++) {
#pragma unroll
        for (int c = 0; c < CHNK; c++) {
            v[j][c] = __ldcs(reinterpret_cast<const float4*>(xs[j] + base + c * 128));
        }
    }

    float p[LL];
#pragma unroll
    for (int j = 0; j < LL; j++) {
        float a0 = (v[j][0].x + v[j][0].y) + (v[j][0].z + v[j][0].w);
        float a1 = (v[j][1].x + v[j][1].y) + (v[j][1].z + v[j][1].w);
        float a2 = (v[j][2].x + v[j][2].y) + (v[j][2].z + v[j][2].w);
        float a3 = (v[j][3].x + v[j][3].y) + (v[j][3].z + v[j][3].w);
        p[j] = (a0 + a1) + (a2 + a3);
    }

    // Warp butterfly: all lanes end with the full per-layer sums.
    // (redux.sync.add is integer-only on sm_103 — shuffle tree required.)
#pragma unroll
    for (int off = 16; off > 0; off >>= 1) {
#pragma unroll
        for (int j = 0; j < LL; j++) {
            p[j] += __shfl_xor_sync(0xffffffffu, p[j], off);
        }
    }

    // Redundant per-lane 6x6 projection + softmax (warp-uniform Ws loads;
    // Ws is 73KB total, L2/L1 hot).
    const float* W = Ws + (size_t)s * (LL * LL);
    float logit[LL];
#pragma unroll
    for (int m = 0; m < LL; m++) logit[m] = 0.0f;
#pragma unroll
    for (int l = 0; l < LL; l++) {
        const float sl = p[l];
#pragma unroll
        for (int m = 0; m < LL; m++) {
            logit[m] = fmaf(sl, __ldg(W + l * LL + m), logit[m]);
        }
    }

    float mx = logit[0];
#pragma unroll
    for (int m = 1; m < LL; m++) mx = fmaxf(mx, logit[m]);
    float a[LL];
    float den = 0.0f;
#pragma unroll
    for (int m = 0; m < LL; m++) {
        a[m] = __expf(logit[m] - mx);
        den += a[m];
    }
    const float inv = __frcp_rn(den);
#pragma unroll
    for (int m = 0; m < LL; m++) a[m] *= inv;

    // Weighted combine over layers, 4 coalesced streaming stores.
#pragma unroll
    for (int c = 0; c < CHNK; c++) {
        float4 o;
        o.x = o.y = o.z = o.w = 0.0f;
#pragma unroll
        for (int j = 0; j < LL; j++) {
            o.x = fmaf(a[j], v[j][c].x, o.x);
            o.y = fmaf(a[j], v[j][c].y, o.y);
            o.z = fmaf(a[j], v[j][c].z, o.z);
            o.w = fmaf(a[j], v[j][c].w, o.w);
        }
        __stcs(reinterpret_cast<float4*>(out + base + c * 128), o);
    }
}

extern "C" void kernel_launch(void* const* d_in, const int* in_sizes, int n_in,
                              void* d_out, int out_size)
{
    const float* x0 = (const float*)d_in[0];
    const float* x1 = (const float*)d_in[1];
    const float* x2 = (const float*)d_in[2];
    const float* x3 = (const float*)d_in[3];
    const float* x4 = (const float*)d_in[4];
    const float* x5 = (const float*)d_in[5];
    const float* Ws = (const float*)d_in[6];
    float* out = (float*)d_out;

    const int rows = in_sizes[0] / DD;          // B*S = 32768
    dense_att_kernel<<<rows, NTHR>>>(x0, x1, x2, x3, x4, x5, Ws, out);
}